// round 1
// baseline (speedup 1.0000x reference)
#include <cuda_runtime.h>
#include <cstdint>
#include <cstddef>

// Problem constants (fixed by the dataset)
#define B 32
#define P 24564
#define T 50
#define C 81
#define BP (B * P)

// ---------------- scratch (__device__ globals; no allocations allowed) ------
__device__ unsigned long long g_bp_key[B * T];   // packed (iou_bits<<32)|(~prior)
__device__ unsigned char g_match[BP];            // bit7 = (best_ov>=0.5), bits0-6 = best_truth_idx
__device__ unsigned char g_conf[BP];             // conf_t target class (0 = background)
__device__ float g_mine[BP];                     // ce for negatives, 0 for positives
__device__ int   g_npos[B];
__device__ float g_lossl[B];
__device__ float g_losscpos[B];
__device__ float g_losscneg[B];

// ---------------- init ------------------------------------------------------
__global__ void k_init() {
    int i = blockIdx.x * blockDim.x + threadIdx.x;
    if (i < B * T) g_bp_key[i] = 0ull;
    if (i < B) {
        g_npos[i] = 0;
        g_lossl[i] = 0.f;
        g_losscpos[i] = 0.f;
        g_losscneg[i] = 0.f;
    }
}

// ---------------- kernel 1: IoU matching ------------------------------------
// grid (12 tiles, B), 256 threads. Each thread holds 8 priors in registers.
#define K1_TILE 2048
#define K1_THREADS 256
#define PPT (K1_TILE / K1_THREADS)   // 8

__global__ void __launch_bounds__(K1_THREADS)
k_match(const float* __restrict__ priors, const float* __restrict__ boxes) {
    const int b = blockIdx.y;
    const int tile0 = blockIdx.x * K1_TILE;
    const int tid = threadIdx.x;

    __shared__ float4 s_tr[T];
    __shared__ float  s_ta[T];
    __shared__ unsigned long long s_bp[T];

    if (tid < T) {
        const float4 tr = reinterpret_cast<const float4*>(boxes)[b * T + tid];
        s_tr[tid] = tr;
        // area exactly as reference: (x2-x1)*(y2-y1)
        s_ta[tid] = __fmul_rn(__fsub_rn(tr.z, tr.x), __fsub_rn(tr.w, tr.y));
        s_bp[tid] = 0ull;
    }
    __syncthreads();

    float px1[PPT], py1[PPT], px2[PPT], py2[PPT], pa[PPT];
    float bq[PPT];
    int   bi[PPT];
    bool  valid[PPT];
    const int pidx0 = tile0 + tid;

#pragma unroll
    for (int i = 0; i < PPT; i++) {
        const int p = pidx0 + i * K1_THREADS;
        valid[i] = (p < P);
        bq[i] = -1.f;
        bi[i] = 0;
        if (valid[i]) {
            const float4 pr = reinterpret_cast<const float4*>(priors)[p];
            // point form: cx -/+ w/2 (divide by 2 == *0.5, exact)
            const float hw = __fmul_rn(pr.z, 0.5f);
            const float hh = __fmul_rn(pr.w, 0.5f);
            px1[i] = __fsub_rn(pr.x, hw);
            py1[i] = __fsub_rn(pr.y, hh);
            px2[i] = __fadd_rn(pr.x, hw);
            py2[i] = __fadd_rn(pr.y, hh);
            pa[i]  = __fmul_rn(__fsub_rn(px2[i], px1[i]), __fsub_rn(py2[i], py1[i]));
        } else {
            px1[i] = 1e30f; py1[i] = 1e30f; px2[i] = 1e30f; py2[i] = 1e30f; pa[i] = 1.f;
        }
    }

    for (int t = 0; t < T; t++) {
        const float4 tr = s_tr[t];
        const float ta = s_ta[t];
        float ltq = -1.f;
        int   ltp = 0;
#pragma unroll
        for (int i = 0; i < PPT; i++) {
            const float lx = fmaxf(tr.x, px1[i]);
            const float ly = fmaxf(tr.y, py1[i]);
            const float rx = fminf(tr.z, px2[i]);
            const float ry = fminf(tr.w, py2[i]);
            const float w = fmaxf(__fsub_rn(rx, lx), 0.f);
            const float h = fmaxf(__fsub_rn(ry, ly), 0.f);
            const float inter = __fmul_rn(w, h);
            float q = 0.f;
            if (inter > 0.f) {
                const float den = __fsub_rn(__fadd_rn(ta, pa[i]), inter);
                q = __fdiv_rn(inter, den);
            }
            if (q > bq[i]) { bq[i] = q; bi[i] = t; }           // first-t wins ties
            if (valid[i] && (q > ltq)) { ltq = q; ltp = pidx0 + i * K1_THREADS; }
        }
        // warp-reduce per-truth best: larger q wins, tie -> smaller prior idx
#pragma unroll
        for (int off = 16; off; off >>= 1) {
            const float oq = __shfl_down_sync(0xffffffffu, ltq, off);
            const int   op = __shfl_down_sync(0xffffffffu, ltp, off);
            if (oq > ltq || (oq == ltq && op < ltp)) { ltq = oq; ltp = op; }
        }
        if ((tid & 31) == 0 && ltq >= 0.f) {
            const unsigned long long key =
                ((unsigned long long)__float_as_uint(ltq) << 32) |
                (unsigned long long)(0xFFFFFFFFu - (unsigned)ltp);
            atomicMax(&s_bp[t], key);
        }
    }

#pragma unroll
    for (int i = 0; i < PPT; i++) {
        if (valid[i]) {
            const int p = pidx0 + i * K1_THREADS;
            unsigned char m = (unsigned char)bi[i];
            if (bq[i] >= 0.5f) m |= 0x80;
            g_match[(size_t)b * P + p] = m;
        }
    }
    __syncthreads();
    if (tid < T) atomicMax(&g_bp_key[b * T + tid], s_bp[tid]);
}

// ---------------- kernel 2: forcing + targets + localization loss -----------
__global__ void k_target(const float* __restrict__ loc,
                         const float* __restrict__ priors,
                         const float* __restrict__ boxes,
                         const int* __restrict__ labels) {
    const int b = blockIdx.y;
    const int tid = threadIdx.x;

    __shared__ int    s_bp[T];
    __shared__ float4 s_tr[T];
    __shared__ int    s_lb[T];

    if (tid < T) {
        const unsigned long long key = g_bp_key[b * T + tid];
        s_bp[tid] = (int)(0xFFFFFFFFu - (unsigned)(key & 0xFFFFFFFFull));
        s_tr[tid] = reinterpret_cast<const float4*>(boxes)[b * T + tid];
        s_lb[tid] = labels[b * T + tid];
    }
    __syncthreads();

    const int p = blockIdx.x * blockDim.x + tid;
    if (p >= P) return;
    const size_t gp = (size_t)b * P + p;

    const unsigned char m = g_match[gp];
    int  idx = m & 0x7F;
    bool pos = (m & 0x80) != 0;
    // sequential scatter semantics: later t overwrites (last wins)
#pragma unroll
    for (int t = 0; t < T; t++) {
        if (s_bp[t] == p) { idx = t; pos = true; }
    }
    const int conf = pos ? (s_lb[idx] + 1) : 0;
    g_conf[gp] = (unsigned char)conf;

    if (pos) {
        const float4 tr = s_tr[idx];
        const float4 pr = reinterpret_cast<const float4*>(priors)[p];
        const float gx = ((tr.x + tr.z) * 0.5f - pr.x) / (0.1f * pr.z);
        const float gy = ((tr.y + tr.w) * 0.5f - pr.y) / (0.1f * pr.w);
        const float gw = logf((tr.z - tr.x) / pr.z) / 0.2f;
        const float gh = logf((tr.w - tr.y) / pr.w) / 0.2f;
        const float4 l = reinterpret_cast<const float4*>(loc)[gp];
        float tgt[4] = {gx, gy, gw, gh};
        float lv[4] = {l.x, l.y, l.z, l.w};
        float loss = 0.f;
#pragma unroll
        for (int j = 0; j < 4; j++) {
            const float d = lv[j] - tgt[j];
            const float ad = fabsf(d);
            loss += (ad < 1.f) ? 0.5f * d * d : ad - 0.5f;
        }
        atomicAdd(&g_lossl[b], loss);
        atomicAdd(&g_npos[b], 1);
    }
}

// ---------------- kernel 3: cross entropy (warp per prior) ------------------
__global__ void k_ce(const float* __restrict__ conf) {
    const int w = blockIdx.x * (blockDim.x >> 5) + (threadIdx.x >> 5);
    const int lane = threadIdx.x & 31;
    if (w >= BP) return;
    const float* row = conf + (size_t)w * C;

    const float v0 = row[lane];
    const float v1 = row[32 + lane];
    const float v2 = (lane < 17) ? row[64 + lane] : -3.4e38f;

    float m = fmaxf(fmaxf(v0, v1), v2);
#pragma unroll
    for (int off = 16; off; off >>= 1)
        m = fmaxf(m, __shfl_xor_sync(0xffffffffu, m, off));

    float s = __expf(v0 - m) + __expf(v1 - m) + ((lane < 17) ? __expf(v2 - m) : 0.f);
#pragma unroll
    for (int off = 16; off; off >>= 1)
        s += __shfl_xor_sync(0xffffffffu, s, off);

    if (lane == 0) {
        const int c = g_conf[w];
        const float ce = m + __logf(s) - row[c];
        const int b = w / P;
        if (c > 0) {
            atomicAdd(&g_losscpos[b], ce);
            g_mine[w] = 0.f;
        } else {
            g_mine[w] = fmaxf(ce, 0.f);   // clamp: radix-select needs nonneg bits
        }
    }
}

// ---------------- kernel 4: per-batch top-k sum via radix select ------------
__global__ void __launch_bounds__(1024) k_mine_sel() {
    const int b = blockIdx.x;
    const int tid = threadIdx.x;
    __shared__ int hist[256];
    __shared__ int scan_[256];
    __shared__ unsigned sh_prefix;
    __shared__ int sh_want;
    __shared__ int sh_digit;
    __shared__ float sh_sum;
    __shared__ int sh_cnt;

    const float* mine = g_mine + (size_t)b * P;
    const int npos = g_npos[b];
    int k = 3 * npos;
    if (k > P - 1) k = P - 1;

    if (tid == 0) { sh_prefix = 0u; sh_want = k; sh_sum = 0.f; sh_cnt = 0; }
    __syncthreads();

    for (int shift = 24; shift >= 0; shift -= 8) {
        if (tid < 256) hist[tid] = 0;
        __syncthreads();
        const unsigned pref = sh_prefix;
        for (int i = tid; i < P; i += blockDim.x) {
            const unsigned key = __float_as_uint(mine[i]);
            const bool match = (shift == 24) || ((key >> (shift + 8)) == pref);
            if (match) atomicAdd(&hist[(key >> shift) & 0xFFu], 1);
        }
        __syncthreads();
        if (tid < 256) scan_[tid] = hist[tid];
        __syncthreads();
        // suffix sum: scan_[d] = count of matching keys with digit >= d
        for (int off = 1; off < 256; off <<= 1) {
            int v = 0;
            if (tid < 256) v = scan_[tid] + ((tid + off < 256) ? scan_[tid + off] : 0);
            __syncthreads();
            if (tid < 256) scan_[tid] = v;
            __syncthreads();
        }
        const int want = sh_want;
        if (tid < 256) {
            const int ge = scan_[tid];
            const int gt = (tid < 255) ? scan_[tid + 1] : 0;
            if (ge >= want && gt < want) sh_digit = tid;   // unique (monotone)
        }
        __syncthreads();
        if (tid == 0) {
            const int d = sh_digit;
            const int gt = (d < 255) ? scan_[d + 1] : 0;
            sh_want = want - gt;
            sh_prefix = (shift == 24) ? (unsigned)d : ((sh_prefix << 8) | (unsigned)d);
        }
        __syncthreads();
    }

    const unsigned vb = sh_prefix;   // bits of the k-th largest value (exact)
    float sum = 0.f;
    int cnt = 0;
    for (int i = tid; i < P; i += blockDim.x) {
        const float v = mine[i];
        if (__float_as_uint(v) > vb) { sum += v; cnt++; }
    }
#pragma unroll
    for (int off = 16; off; off >>= 1) {
        sum += __shfl_down_sync(0xffffffffu, sum, off);
        cnt += __shfl_down_sync(0xffffffffu, cnt, off);
    }
    if ((tid & 31) == 0) {
        atomicAdd(&sh_sum, sum);
        atomicAdd(&sh_cnt, cnt);
    }
    __syncthreads();
    if (tid == 0) {
        // tie-invariant: sum(top-k) = sum(>v) + (k - count_gt) * v
        g_losscneg[b] = sh_sum + (float)(k - sh_cnt) * __uint_as_float(vb);
    }
}

// ---------------- kernel 5: finalize ----------------------------------------
__global__ void k_final(float* __restrict__ out) {
    const int tid = threadIdx.x;   // 32 threads
    int   np = (tid < B) ? g_npos[tid] : 0;
    float ll = (tid < B) ? g_lossl[tid] : 0.f;
    float lc = (tid < B) ? (g_losscpos[tid] + g_losscneg[tid]) : 0.f;
#pragma unroll
    for (int off = 16; off; off >>= 1) {
        np += __shfl_down_sync(0xffffffffu, np, off);
        ll += __shfl_down_sync(0xffffffffu, ll, off);
        lc += __shfl_down_sync(0xffffffffu, lc, off);
    }
    if (tid == 0) {
        const float N = (float)np;
        out[0] = ll / N;
        out[1] = lc / N;
    }
}

// ---------------- launch ----------------------------------------------------
extern "C" void kernel_launch(void* const* d_in, const int* in_sizes, int n_in,
                              void* d_out, int out_size) {
    const float* loc    = (const float*)d_in[0];
    const float* conf   = (const float*)d_in[1];
    const float* priors = (const float*)d_in[2];
    const float* boxes  = (const float*)d_in[3];
    const int*   labels = (const int*)d_in[4];
    float* out = (float*)d_out;

    k_init<<<2, 1024>>>();

    dim3 g1((P + K1_TILE - 1) / K1_TILE, B);      // (12, 32)
    k_match<<<g1, K1_THREADS>>>(priors, boxes);

    dim3 g2((P + 255) / 256, B);
    k_target<<<g2, 256>>>(loc, priors, boxes, labels);

    k_ce<<<(BP + 7) / 8, 256>>>(conf);            // 8 warps/block, warp per prior

    k_mine_sel<<<B, 1024>>>();

    k_final<<<1, 32>>>(out);
}